// round 6
// baseline (speedup 1.0000x reference)
#include <cuda_runtime.h>
#include <cuda_fp16.h>

#define BATCH 16
#define C_IN  64
#define C_OUT 32
#define V_HI  163842
#define V_LO  40962
#define KNB   7

#define TILE_V 64
#define VTILES ((V_LO + TILE_V - 1) / TILE_V)   // 641
#define CHUNK_B 4                               // 84MB out window, L2-resident
#define OG 4                                    // o-groups per block
#define O_PER (C_OUT / OG)                      // 8 channels per thread

// Precomputed neigh table: g_neigh8[v*8+k] = up_neigh[down[v]*7 + k], stride 8.
__device__ int g_neigh8[V_LO * 8];

__global__ void build_neigh_kernel(const int* __restrict__ up_neigh,
                                   const int* __restrict__ down) {
    int v = blockIdx.x * blockDim.x + threadIdx.x;
    if (v >= V_LO) return;
    int dv = down[v];
    const int* src = up_neigh + (long long)dv * KNB;
#pragma unroll
    for (int k = 0; k < KNB; k++) g_neigh8[v * 8 + k] = src[k];
    g_neigh8[v * 8 + 7] = 0;
}

// Fused GEMV + packed-atomicMax scatter, occupancy-optimized:
// block = 64 vertices x 4 o-groups; each thread owns 8 channels => h[8] only,
// ~40 regs, 6+ blocks/SM. x tile staged in smem (16KB). Chunk's out window was
// just memset -> L2-dirty-resident, atomics are L2 hits. Winner = largest v
// (reference last-write-wins; collisions only within one (b,o) slice).
__global__ __launch_bounds__(256) void fused_gemm_scatter_kernel(
    const float* __restrict__ x,
    const float* __restrict__ W,
    const float* __restrict__ bias,
    const int*   __restrict__ mpi,
    unsigned int* __restrict__ out32,
    int batch0)
{
    __shared__ float sX[C_IN][TILE_V];      // 16 KB
    __shared__ float sW[C_IN][C_OUT];       // 8 KB
    __shared__ float sB[C_OUT];

    const int tid = threadIdx.x;
    const int b   = batch0 + blockIdx.y;
    const int v0  = blockIdx.x * TILE_V;

    // Load W (transposed) + bias
    for (int i = tid; i < C_IN * C_OUT; i += 256) {
        int o = i / C_IN;
        int c = i % C_IN;
        sW[c][o] = W[i];
    }
    if (tid < C_OUT) sB[tid] = bias[tid];

    // Stage x[b, :, v0:v0+64] (coalesced: 64 consecutive floats per channel row)
    const float* xb = x + (long long)b * C_IN * V_LO;
    for (int i = tid; i < C_IN * TILE_V; i += 256) {
        int c  = i / TILE_V;
        int vl = i % TILE_V;
        int v  = v0 + vl;
        sX[c][vl] = (v < V_LO) ? __ldg(xb + (long long)c * V_LO + v) : 0.0f;
    }
    __syncthreads();

    const int vl = tid & (TILE_V - 1);      // 0..63
    const int og = tid >> 6;                // 0..3
    const int o0 = og * O_PER;
    const int v  = v0 + vl;
    if (v >= V_LO) return;

    // h[j] = bias[o0+j] + sum_c sW[c][o0+j] * sX[c][vl]
    float h[O_PER];
#pragma unroll
    for (int j = 0; j < O_PER; j++) h[j] = sB[o0 + j];

#pragma unroll 8
    for (int c = 0; c < C_IN; c++) {
        float xc = sX[c][vl];
#pragma unroll
        for (int j = 0; j < O_PER; j++) h[j] = fmaf(xc, sW[c][o0 + j], h[j]);
    }

    const unsigned int vtag = ((unsigned int)(v + 1)) << 16;
    const int* mp = mpi + ((long long)b * C_OUT + o0) * V_LO + v;
    const int* nr = &g_neigh8[v * 8];                 // 32B row, L1-resident
    unsigned int* ob = out32 + ((long long)b * C_OUT + o0) * V_HI;

#pragma unroll
    for (int j = 0; j < O_PER; j++) {
        int k = __ldg(mp + (long long)j * V_LO);      // coalesced per j
        int u = __ldg(nr + k);                        // L1 hit
        unsigned short hb = __half_as_ushort(__float2half_rn(h[j]));
        atomicMax(&ob[(long long)j * V_HI + u], vtag | (unsigned int)hb);  // L2 hit
    }
}

// In-place decode: 0 -> 0.0f, else float(fp16 low half). Vectorized uint4/float4.
// Runs per chunk while the chunk's lines are still L2-resident.
__global__ __launch_bounds__(256) void finalize_kernel(unsigned int* __restrict__ buf,
                                                       long long n4)
{
    long long i = (long long)blockIdx.x * blockDim.x + threadIdx.x;
    if (i >= n4) return;
    uint4 p = reinterpret_cast<uint4*>(buf)[i];
    float4 f;
    f.x = p.x ? __half2float(__ushort_as_half((unsigned short)(p.x & 0xFFFFu))) : 0.0f;
    f.y = p.y ? __half2float(__ushort_as_half((unsigned short)(p.y & 0xFFFFu))) : 0.0f;
    f.z = p.z ? __half2float(__ushort_as_half((unsigned short)(p.z & 0xFFFFu))) : 0.0f;
    f.w = p.w ? __half2float(__ushort_as_half((unsigned short)(p.w & 0xFFFFu))) : 0.0f;
    reinterpret_cast<float4*>(buf)[i] = f;
}

extern "C" void kernel_launch(void* const* d_in, const int* in_sizes, int n_in,
                              void* d_out, int out_size) {
    const float* x    = (const float*)d_in[0];   // (16, 64, 40962) f32
    const float* W    = (const float*)d_in[1];   // (32, 64) f32
    const float* bias = (const float*)d_in[2];   // (32,) f32
    const int*   mpi  = (const int*)d_in[3];     // (16, 32, 40962) i32
    const int*   up   = (const int*)d_in[4];     // (163842, 7) i32
    const int*   down = (const int*)d_in[5];     // (40962,) i32

    unsigned int* out32 = (unsigned int*)d_out;  // aliases the f32 output buffer

    build_neigh_kernel<<<(V_LO + 255) / 256, 256>>>(up, down);

    const long long chunk_elems = (long long)CHUNK_B * C_OUT * V_HI;
    const long long n4 = chunk_elems / 4;
    const unsigned fin_grid = (unsigned)((n4 + 255) / 256);

    for (int c = 0; c < BATCH; c += CHUNK_B) {
        unsigned int* chunk_ptr = out32 + (long long)c * C_OUT * V_HI;

        // 1) zero this chunk's window (atomicMax identity; lines become L2-dirty)
        cudaMemsetAsync(chunk_ptr, 0, (size_t)chunk_elems * sizeof(unsigned int), 0);

        // 2) fused GEMV + packed atomicMax scatter into the L2-resident window
        dim3 grid(VTILES, CHUNK_B);
        fused_gemm_scatter_kernel<<<grid, 256>>>(x, W, bias, mpi, out32, c);

        // 3) decode this chunk to float while still L2-resident
        finalize_kernel<<<fin_grid, 256>>>(chunk_ptr, n4);
    }
}

// round 7
// speedup vs baseline: 1.0776x; 1.0776x over previous
#include <cuda_runtime.h>
#include <cuda_fp16.h>

#define BATCH 16
#define C_IN  64
#define C_OUT 32
#define V_HI  163842
#define V_LO  40962
#define KNB   7

#define TILES ((V_LO + 255) / 256)      // 161 tiles of 256 vertices
#define CHUNK_B 4                        // 84MB out window, L2-resident

// Precomputed neigh table: g_neigh8[v*8+k] = up_neigh[down[v]*7 + k], stride 8.
__device__ int g_neigh8[V_LO * 8];

__global__ void build_neigh_kernel(const int* __restrict__ up_neigh,
                                   const int* __restrict__ down) {
    int v = blockIdx.x * blockDim.x + threadIdx.x;
    if (v >= V_LO) return;
    int dv = down[v];
    const int* src = up_neigh + (long long)dv * KNB;
#pragma unroll
    for (int k = 0; k < KNB; k++) g_neigh8[v * 8 + k] = src[k];
    g_neigh8[v * 8 + 7] = 0;
}

// Fused GEMV + packed-atomicMax scatter (R5 mapping: thread owns a vertex and
// all 32 channels). Neighbor rows for the 256-vertex tile are staged into smem
// via coalesced int4 loads, turning the previously uncoalesced per-o gather
// (32 LSU transactions/warp) into a ~3-cycle LDS. Chunk's out window is
// L2-dirty-resident from the preceding zeroing pass, so atomics are L2 hits.
// Winner = largest v (reference sequential last-write-wins; collisions only
// within one (b,o) slice).
__global__ __launch_bounds__(256) void fused_gemm_scatter_kernel(
    const float* __restrict__ x,
    const float* __restrict__ W,
    const float* __restrict__ bias,
    const int*   __restrict__ mpi,
    unsigned int* __restrict__ out32,
    int batch0)
{
    __shared__ float sW[C_IN][C_OUT + 1];   // transposed, padded (8.4 KB)
    __shared__ float sB[C_OUT];
    __shared__ int   sN[256][8];             // neighbor rows for this tile (8 KB)

    const int tid = threadIdx.x;
    const int v0  = blockIdx.x * 256;
    const int v   = v0 + tid;
    const int b   = batch0 + blockIdx.y;

    for (int i = tid; i < C_IN * C_OUT; i += 256) {
        int o = i / C_IN;
        int c = i % C_IN;
        sW[c][o] = W[i];
    }
    if (tid < C_OUT) sB[tid] = bias[tid];

    // Stage this tile's neighbor rows: 2 coalesced int4 loads per thread.
    {
        int vv = (v < V_LO) ? v : (V_LO - 1);
        const int4* src = reinterpret_cast<const int4*>(&g_neigh8[vv * 8]);
        int4* dst = reinterpret_cast<int4*>(&sN[tid][0]);
        dst[0] = src[0];
        dst[1] = src[1];
    }
    __syncthreads();

    if (v >= V_LO) return;

    // GEMV slice: h[o] = bias[o] + sum_c W[o][c] * x[b][c][v]
    float h[C_OUT];
#pragma unroll
    for (int o = 0; o < C_OUT; o++) h[o] = sB[o];

    const float* xp = x + ((long long)b * C_IN) * V_LO + v;
#pragma unroll
    for (int c = 0; c < C_IN; c++) {
        float xc = __ldg(xp + (long long)c * V_LO);
#pragma unroll
        for (int o = 0; o < C_OUT; o++) h[o] = fmaf(xc, sW[c][o], h[o]);
    }

    const unsigned int vtag = ((unsigned int)(v + 1)) << 16;
    const int* mp = mpi + ((long long)b * C_OUT) * V_LO + v;
    unsigned int* ob = out32 + ((long long)b * C_OUT) * V_HI;

#pragma unroll
    for (int o = 0; o < C_OUT; o++) {
        int k = __ldg(mp + (long long)o * V_LO);   // coalesced
        int u = sN[tid][k];                        // LDS, ~2-3 way conflicts
        unsigned short hb = __half_as_ushort(__float2half_rn(h[o]));
        atomicMax(&ob[(long long)o * V_HI + u], vtag | (unsigned int)hb);  // L2 hit
    }
}

// Decode chunk c in place (0 -> 0.0f, else fp16 low half -> f32) AND zero the
// next chunk's window (replaces a separate memset launch). Vectorized uint4.
__global__ __launch_bounds__(256) void finalize_zero_kernel(
    unsigned int* __restrict__ buf,
    unsigned int* __restrict__ nextbuf,   // may be null
    long long n4)
{
    long long i = (long long)blockIdx.x * blockDim.x + threadIdx.x;
    if (i >= n4) return;
    uint4 p = reinterpret_cast<uint4*>(buf)[i];
    float4 f;
    f.x = p.x ? __half2float(__ushort_as_half((unsigned short)(p.x & 0xFFFFu))) : 0.0f;
    f.y = p.y ? __half2float(__ushort_as_half((unsigned short)(p.y & 0xFFFFu))) : 0.0f;
    f.z = p.z ? __half2float(__ushort_as_half((unsigned short)(p.z & 0xFFFFu))) : 0.0f;
    f.w = p.w ? __half2float(__ushort_as_half((unsigned short)(p.w & 0xFFFFu))) : 0.0f;
    reinterpret_cast<float4*>(buf)[i] = f;
    if (nextbuf) {
        reinterpret_cast<uint4*>(nextbuf)[i] = make_uint4(0u, 0u, 0u, 0u);
    }
}

extern "C" void kernel_launch(void* const* d_in, const int* in_sizes, int n_in,
                              void* d_out, int out_size) {
    const float* x    = (const float*)d_in[0];   // (16, 64, 40962) f32
    const float* W    = (const float*)d_in[1];   // (32, 64) f32
    const float* bias = (const float*)d_in[2];   // (32,) f32
    const int*   mpi  = (const int*)d_in[3];     // (16, 32, 40962) i32
    const int*   up   = (const int*)d_in[4];     // (163842, 7) i32
    const int*   down = (const int*)d_in[5];     // (40962,) i32

    unsigned int* out32 = (unsigned int*)d_out;  // aliases the f32 output buffer

    const long long chunk_elems = (long long)CHUNK_B * C_OUT * V_HI;
    const long long n4 = chunk_elems / 4;
    const unsigned fin_grid = (unsigned)((n4 + 255) / 256);

    // Zero chunk 0's window; build neighbor table.
    cudaMemsetAsync(out32, 0, (size_t)chunk_elems * sizeof(unsigned int), 0);
    build_neigh_kernel<<<(V_LO + 255) / 256, 256>>>(up, down);

    for (int c = 0; c < BATCH; c += CHUNK_B) {
        unsigned int* chunk_ptr = out32 + (long long)c * C_OUT * V_HI;
        unsigned int* next_ptr  = (c + CHUNK_B < BATCH)
                                ? chunk_ptr + chunk_elems : (unsigned int*)0;

        // fused GEMV + packed atomicMax scatter into the L2-resident window
        dim3 grid(TILES, CHUNK_B);
        fused_gemm_scatter_kernel<<<grid, 256>>>(x, W, bias, mpi, out32, c);

        // decode this chunk (L2-resident) + zero the next chunk's window
        finalize_zero_kernel<<<fin_grid, 256>>>(chunk_ptr, next_ptr, n4);
    }
}

// round 8
// speedup vs baseline: 1.1790x; 1.0940x over previous
#include <cuda_runtime.h>
#include <cuda_fp16.h>

#define BATCH 16
#define C_IN  64
#define C_OUT 32
#define V_HI  163842
#define V_LO  40962
#define KNB   7

#define TILES ((V_LO + 255) / 256)   // 161 tiles of 256 vertices
#define OSPLIT 2                     // o-dimension split across blockIdx.z
#define O_PER (C_OUT / OSPLIT)       // 16 channels per thread

// Precomputed neigh table: g_neigh8[v*8+k] = up_neigh[down[v]*7 + k], stride 8.
__device__ int g_neigh8[V_LO * 8];

__global__ void build_neigh_kernel(const int* __restrict__ up_neigh,
                                   const int* __restrict__ down) {
    int v = blockIdx.x * blockDim.x + threadIdx.x;
    if (v >= V_LO) return;
    int dv = down[v];
    const int* src = up_neigh + (long long)dv * KNB;
#pragma unroll
    for (int k = 0; k < KNB; k++) g_neigh8[v * 8 + k] = src[k];
    g_neigh8[v * 8 + 7] = 0;
}

// Fused GEMV + packed-atomicMax scatter. One launch covers all 16 batches
// (full waves, no per-chunk tail drain). o-dimension split across blockIdx.z:
// each thread owns 16 channels -> ~52 regs -> 5 blocks/SM. Winner = largest v
// (reference sequential last-write-wins; collisions only within one (b,o)).
__global__ __launch_bounds__(256) void fused_gemm_scatter_kernel(
    const float* __restrict__ x,
    const float* __restrict__ W,
    const float* __restrict__ bias,
    const int*   __restrict__ mpi,
    unsigned int* __restrict__ out32)
{
    __shared__ float sW[C_IN][C_OUT + 1];   // transposed, padded
    __shared__ float sB[C_OUT];

    const int tid = threadIdx.x;
    const int b   = blockIdx.y;
    const int o0  = blockIdx.z * O_PER;

    for (int i = tid; i < C_IN * C_OUT; i += 256) {
        int o = i / C_IN;
        int c = i % C_IN;
        sW[c][o] = W[i];
    }
    if (tid < C_OUT) sB[tid] = bias[tid];
    __syncthreads();

    const int v = blockIdx.x * 256 + tid;
    if (v >= V_LO) return;

    // GEMV half-slice: h[j] = bias[o0+j] + sum_c W[o0+j][c] * x[b][c][v]
    float h[O_PER];
#pragma unroll
    for (int j = 0; j < O_PER; j++) h[j] = sB[o0 + j];

    const float* xp = x + ((long long)b * C_IN) * V_LO + v;
#pragma unroll
    for (int c = 0; c < C_IN; c++) {
        float xc = __ldg(xp + (long long)c * V_LO);
#pragma unroll
        for (int j = 0; j < O_PER; j++) h[j] = fmaf(xc, sW[c][o0 + j], h[j]);
    }

    // 7 neighbor ids for this v (32B aligned, coalesced across threads).
    const int4* np = reinterpret_cast<const int4*>(&g_neigh8[v * 8]);
    int4 n0 = np[0];
    int4 n1 = np[1];
    int nb[8] = {n0.x, n0.y, n0.z, n0.w, n1.x, n1.y, n1.z, n1.w};

    const unsigned int vtag = ((unsigned int)(v + 1)) << 16;
    const int* mp = mpi + ((long long)b * C_OUT + o0) * V_LO + v;
    unsigned int* ob = out32 + ((long long)b * C_OUT + o0) * V_HI;

#pragma unroll
    for (int j = 0; j < O_PER; j++) {
        int k = __ldg(mp + (long long)j * V_LO);   // coalesced
        int u = nb[k];
        unsigned short hb = __half_as_ushort(__float2half_rn(h[j]));
        atomicMax(&ob[(long long)j * V_HI + u], vtag | (unsigned int)hb);  // RED.MAX.U32
    }
}

// In-place decode: 0 -> 0.0f, else float(fp16 low half). Vectorized uint4/float4.
__global__ __launch_bounds__(256) void finalize_kernel(unsigned int* __restrict__ buf,
                                                       long long n4)
{
    long long i = (long long)blockIdx.x * blockDim.x + threadIdx.x;
    if (i >= n4) return;
    uint4 p = reinterpret_cast<uint4*>(buf)[i];
    float4 f;
    f.x = p.x ? __half2float(__ushort_as_half((unsigned short)(p.x & 0xFFFFu))) : 0.0f;
    f.y = p.y ? __half2float(__ushort_as_half((unsigned short)(p.y & 0xFFFFu))) : 0.0f;
    f.z = p.z ? __half2float(__ushort_as_half((unsigned short)(p.z & 0xFFFFu))) : 0.0f;
    f.w = p.w ? __half2float(__ushort_as_half((unsigned short)(p.w & 0xFFFFu))) : 0.0f;
    reinterpret_cast<float4*>(buf)[i] = f;
}

extern "C" void kernel_launch(void* const* d_in, const int* in_sizes, int n_in,
                              void* d_out, int out_size) {
    const float* x    = (const float*)d_in[0];   // (16, 64, 40962) f32
    const float* W    = (const float*)d_in[1];   // (32, 64) f32
    const float* bias = (const float*)d_in[2];   // (32,) f32
    const int*   mpi  = (const int*)d_in[3];     // (16, 32, 40962) i32
    const int*   up   = (const int*)d_in[4];     // (163842, 7) i32
    const int*   down = (const int*)d_in[5];     // (40962,) i32

    unsigned int* out32 = (unsigned int*)d_out;  // aliases the f32 output buffer

    // 1) zero output (atomicMax identity; required every call — buffer persists)
    cudaMemsetAsync(d_out, 0, (size_t)out_size * sizeof(float), 0);

    // 2) build effective neighbor table
    build_neigh_kernel<<<(V_LO + 255) / 256, 256>>>(up, down);

    // 3) fused GEMV + packed atomicMax scatter, one full-width launch
    dim3 grid(TILES, BATCH, OSPLIT);
    fused_gemm_scatter_kernel<<<grid, 256>>>(x, W, bias, mpi, out32);

    // 4) in-place decode to float
    long long n4 = (long long)out_size / 4;
    finalize_kernel<<<(unsigned)((n4 + 255) / 256), 256>>>(out32, n4);
}